// round 9
// baseline (speedup 1.0000x reference)
#include <cuda_runtime.h>

// Problem constants (fixed by setup_inputs)
#define NB 8
#define CH 256
#define DD 8
#define HH 16
#define WW 16
#define PP 2048            // DD*HH*WW
#define G  2               // channels per block
#define NBLK (NB * (CH / G))   // 1024 blocks, 128 per batch

// Scratch (no allocations allowed)
__device__ float g_partials[NB * CH];
__device__ int   g_cnt[NB];        // per-batch mask counts (int atomics: deterministic)
// Per-voxel run records: 8 x u16: slot0=nruns; slots1..6: bits[0:11)=base, [11:13)=len(1..3)
__device__ __align__(16) unsigned short g_runs16[NB * PP * 8];
__device__ int g_mask_flag[NB];    // chunks done per batch (64 each); reset at end
__device__ int g_done;             // completion ticket; reset at end

// Non-contractable f32 ops: mask predicate must be bit-identical to plain IEEE f32
__device__ __forceinline__ float fm(float a, float b) { return __fmul_rn(a, b); }
__device__ __forceinline__ float fa(float a, float b) { return __fadd_rn(a, b); }
__device__ __forceinline__ float fs(float a, float b) { return __fsub_rn(a, b); }

// ---------------- Mask duty: one voxel; returns positive count ----------------------
__device__ __forceinline__ int mask_voxel(
    int n, int p, const float* __restrict__ cq, const float* __restrict__ ck)
{
    const float x0q = cq[n * 6 + 0], y0q = cq[n * 6 + 1], z0q = cq[n * 6 + 2];
    const float x1q = cq[n * 6 + 3], y1q = cq[n * 6 + 4], z1q = cq[n * 6 + 5];
    const float x0k = ck[n * 6 + 0], y0k = ck[n * 6 + 1], z0k = ck[n * 6 + 2];
    const float x1k = ck[n * 6 + 3], y1k = ck[n * 6 + 4], z1k = ck[n * 6 + 5];

    const float bwq = __fdiv_rn(fs(x1q, x0q), (float)WW);
    const float bhq = __fdiv_rn(fs(y1q, y0q), (float)HH);
    const float bdq = __fdiv_rn(fs(z1q, z0q), (float)DD);
    const float bwk = __fdiv_rn(fs(x1k, x0k), (float)WW);
    const float bhk = __fdiv_rn(fs(y1k, y0k), (float)HH);
    const float bdk = __fdiv_rn(fs(z1k, z0k), (float)DD);

    const float diag_q = __fsqrt_rn(fa(fa(fm(bwq, bwq), fm(bhq, bhq)), fm(bdq, bdq)));
    const float diag_k = __fsqrt_rn(fa(fa(fm(bwk, bwk), fm(bhk, bhk)), fm(bdk, bdk)));
    const float maxdiag = fmaxf(diag_q, diag_k);

    // Candidate windows (widened; fast divides OK — exact predicate filters inside)
    const float r  = 0.5f * maxdiag;
    const float hx = __fdividef(r, bwk) + 0.02f;
    const float hy = __fdividef(r, bhk) + 0.02f;
    const float hz = __fdividef(r, bdk) + 0.02f;

    const int ix = p & 15, iy = (p >> 4) & 15, iz = p >> 8;
    const float cxv = fa(fm((float)ix + 0.5f, bwq), x0q);
    const float cyv = fa(fm((float)iy + 0.5f, bhq), y0q);
    const float czv = fa(fm((float)iz + 0.5f, bdq), z0q);

    const float txc = __fdividef(cxv - x0k, bwk) - 0.5f;
    const float tyc = __fdividef(cyv - y0k, bhk) - 0.5f;
    const float tzc = __fdividef(czv - z0k, bdk) - 0.5f;
    const int jxlo = max(0, (int)ceilf(txc - hx));
    const int jxhi = min(WW - 1, (int)floorf(txc + hx));
    const int jylo = max(0, (int)ceilf(tyc - hy));
    const int jyhi = min(HH - 1, (int)floorf(tyc + hy));
    const int jzlo = max(0, (int)ceilf(tzc - hz));
    const int jzhi = min(DD - 1, (int)floorf(tzc + hz));

    const int base16 = (n * PP + p) * 8;
    int nr = 0, cnt = 0;

    for (int jz = jzlo; jz <= jzhi; jz++) {
        const float dz  = fs(czv, fa(fm((float)jz + 0.5f, bdk), z0k));
        const float dz2 = fm(dz, dz);
        for (int jy = jylo; jy <= jyhi; jy++) {
            const float dy  = fs(cyv, fa(fm((float)jy + 0.5f, bhk), y0k));
            const float dy2 = fm(dy, dy);
            int first = -1, last = -2;
            for (int jx = jxlo; jx <= jxhi; jx++) {
                const float dx = fs(cxv, fa(fm((float)jx + 0.5f, bwk), x0k));
                const float s2 = fa(fa(fm(dx, dx), dy2), dz2);
                // exact reference predicate: sqrt then divide then compare
                if (__fdiv_rn(__fsqrt_rn(s2), maxdiag) < 0.5f) {
                    if (first < 0) first = jx;
                    last = jx;
                }
            }
            if (first >= 0) {
                const int len = last - first + 1;   // <=3 (x-passing set is an interval)
                cnt += len;
                nr++;
                g_runs16[base16 + nr] =
                    (unsigned short)(((jz << 8) + (jy << 4) + first) | (len << 11));
            }
        }
    }
    g_runs16[base16] = (unsigned short)nr;
    return cnt;
}

// ---------------- Fused kernel --------------------------------------------------------
__global__ void __launch_bounds__(256, 7) pixpro_fused(
    const float* __restrict__ q, const float* __restrict__ k,
    const float* __restrict__ cq, const float* __restrict__ ck,
    float* __restrict__ out)
{
    const int bx  = blockIdx.x;
    const int tid = threadIdx.x;
    const int n   = bx >> 7;           // 128 blocks per batch
    const int c0  = (bx & 127) << 1;   // first of 2 channels

    __shared__ float2 ks2[PP];         // 16 KB: 2 channels interleaved per voxel
    __shared__ float  s_wred[8][G];
    __shared__ int    s_elect;
    __shared__ float  s_loss[NB];

    // Phase 0a: mask duty on global blocks bx<512 (always wave-1 resident even at
    // 4 blocks/SM: 592 >= 512). Chunk bx: batch bx>>6, voxels [(bx&63)*32, +32).
    if (bx < 512 && tid < 32) {
        const int mn = bx >> 6;
        const int p  = ((bx & 63) << 5) + tid;
        int cnt = mask_voxel(mn, p, cq, ck);
        #pragma unroll
        for (int off = 16; off > 0; off >>= 1)
            cnt += __shfl_down_sync(0xFFFFFFFFu, cnt, off);
        __syncwarp();
        if (tid == 0) {
            atomicAdd(&g_cnt[mn], cnt);
            __threadfence();
            atomicAdd(&g_mask_flag[mn], 1);
        }
    }

    // Phase 0b: stage k (2 channels -> float2-interleaved smem, conflict-free STS.64)
    const size_t kbase = (size_t)(n * CH + c0) * PP;
    #pragma unroll
    for (int j = 0; j < 8; j++) {
        const int i = tid + (j << 8);
        float2 v;
        v.x = __ldcs(k + kbase + i);
        v.y = __ldcs(k + kbase + PP + i);
        ks2[i] = v;
    }

    // Phase 1: wait for this batch's 64 mask chunks (publishers publish before any
    // spin; all publisher blocks are wave-1 resident)
    if (tid == 0) {
        while (*(volatile int*)&g_mask_flag[n] < 64) __nanosleep(32);
        __threadfence();
    }
    __syncthreads();

    // Phase 2: masked dot for 2 channels; thread owns voxels p = tid + 256*j
    const uint4* __restrict__ rp =
        reinterpret_cast<const uint4*>(g_runs16) + (size_t)n * PP;
    const float* __restrict__ qp = q + (size_t)(n * CH + c0) * PP;

    float l0 = 0.f, l1 = 0.f;
    #pragma unroll
    for (int j = 0; j < 8; j++) {
        const int p = tid + (j << 8);
        const uint4 h  = __ldcg(rp + p);    // L2: fresh run records
        const float q0 = __ldcs(qp + p);
        const float q1 = __ldcs(qp + PP + p);
        const int nr = (int)(h.x & 0xFFFFu);
        float a0 = 0.f, a1 = 0.f;
        #pragma unroll
        for (int s = 1; s <= 6; s++) {
            const unsigned w = (s < 2) ? h.x : ((s < 4) ? h.y : ((s < 6) ? h.z : h.w));
            const unsigned run = (s & 1) ? (w >> 16) : (w & 0xFFFFu);
            const int base = (int)(run & 0x7FFu);
            const int len  = (int)((run >> 11) & 0x3u);
            if (s <= nr) {
                float2 v = ks2[base];
                a0 += v.x; a1 += v.y;
                if (len > 1) { float2 u = ks2[base + 1]; a0 += u.x; a1 += u.y; }
                if (len > 2) { float2 u = ks2[base + 2]; a0 += u.x; a1 += u.y; }
            }
        }
        l0 = fmaf(q0, a0, l0);
        l1 = fmaf(q1, a1, l1);
    }

    // Per-channel deterministic reduction (warp shuffle + fixed-order cross-warp)
    #pragma unroll
    for (int off = 16; off > 0; off >>= 1) {
        l0 += __shfl_down_sync(0xFFFFFFFFu, l0, off);
        l1 += __shfl_down_sync(0xFFFFFFFFu, l1, off);
    }
    if ((tid & 31) == 0) {
        const int w = tid >> 5;
        s_wred[w][0] = l0; s_wred[w][1] = l1;
    }
    __syncthreads();

    // tid 0 writes both partials (so its threadfence orders them), then tickets
    if (tid == 0) {
        #pragma unroll
        for (int g = 0; g < G; g++) {
            float s = 0.f;
            #pragma unroll
            for (int w = 0; w < 8; w++) s += s_wred[w][g];
            g_partials[n * CH + c0 + g] = s;
        }
        __threadfence();
        s_elect = (atomicAdd(&g_done, 1) == NBLK - 1) ? 1 : 0;
    }
    __syncthreads();

    // Phase 3: last-done block finalizes (fixed-order, deterministic)
    if (s_elect) {
        const int w    = tid >> 5;   // batch index
        const int lane = tid & 31;
        float s = 0.f;
        #pragma unroll
        for (int j = 0; j < 8; j++)
            s += __ldcg(&g_partials[w * CH + j * 32 + lane]);
        #pragma unroll
        for (int off = 16; off > 0; off >>= 1)
            s += __shfl_down_sync(0xFFFFFFFFu, s, off);
        if (lane == 0)
            s_loss[w] = s / ((float)__ldcg(&g_cnt[w]) + 1e-6f);
        __syncthreads();
        if (tid == 0) {
            float m = 0.f;
            #pragma unroll
            for (int i = 0; i < NB; i++) m += s_loss[i];
            out[0] = -2.0f * (m * (1.0f / (float)NB));
            // self-reset for next graph replay (all blocks already ticketed)
            #pragma unroll
            for (int i = 0; i < NB; i++) { g_mask_flag[i] = 0; g_cnt[i] = 0; }
            g_done = 0;
        }
    }
}

extern "C" void kernel_launch(void* const* d_in, const int* in_sizes, int n_in,
                              void* d_out, int out_size)
{
    const float* q  = (const float*)d_in[0];
    const float* k  = (const float*)d_in[1];
    const float* cq = (const float*)d_in[2];
    const float* ck = (const float*)d_in[3];
    float* out = (float*)d_out;

    pixpro_fused<<<NBLK, 256>>>(q, k, cq, ck, out);
}

// round 10
// speedup vs baseline: 1.0822x; 1.0822x over previous
#include <cuda_runtime.h>

// Problem constants (fixed by setup_inputs)
#define NB 8
#define CH 256
#define DD 8
#define HH 16
#define WW 16
#define PP 2048            // DD*HH*WW
#define G  4               // channels per block
#define NBLK (NB * (CH / G))   // 512 blocks, 64 per batch
#define NROW (DD * HH)     // 128 rows (z,y), 16 x-values each
#define EW 17              // exclusive-prefix width per row

// Scratch (no allocations allowed)
__device__ float g_partials[NB * CH];
__device__ int   g_cnt[NB];        // per-batch mask counts (int atomics: deterministic)
// Per-voxel run records: 8 x u16: slot0=nruns; slots1..6: bits[0:12)=E-base, [12:14)=len(1..3)
__device__ __align__(16) unsigned short g_runs16[NB * PP * 8];
__device__ int g_mask_flag[NB];    // chunks done per batch (64 each); reset at end
__device__ int g_done;             // completion ticket; reset at end

// Non-contractable f32 ops: mask predicate must be bit-identical to plain IEEE f32
__device__ __forceinline__ float fm(float a, float b) { return __fmul_rn(a, b); }
__device__ __forceinline__ float fa(float a, float b) { return __fadd_rn(a, b); }
__device__ __forceinline__ float fs(float a, float b) { return __fsub_rn(a, b); }

// ---------------- Mask duty: one voxel; returns positive count ----------------------
__device__ __forceinline__ int mask_voxel(
    int n, int p, const float* __restrict__ cq, const float* __restrict__ ck)
{
    const float x0q = cq[n * 6 + 0], y0q = cq[n * 6 + 1], z0q = cq[n * 6 + 2];
    const float x1q = cq[n * 6 + 3], y1q = cq[n * 6 + 4], z1q = cq[n * 6 + 5];
    const float x0k = ck[n * 6 + 0], y0k = ck[n * 6 + 1], z0k = ck[n * 6 + 2];
    const float x1k = ck[n * 6 + 3], y1k = ck[n * 6 + 4], z1k = ck[n * 6 + 5];

    const float bwq = __fdiv_rn(fs(x1q, x0q), (float)WW);
    const float bhq = __fdiv_rn(fs(y1q, y0q), (float)HH);
    const float bdq = __fdiv_rn(fs(z1q, z0q), (float)DD);
    const float bwk = __fdiv_rn(fs(x1k, x0k), (float)WW);
    const float bhk = __fdiv_rn(fs(y1k, y0k), (float)HH);
    const float bdk = __fdiv_rn(fs(z1k, z0k), (float)DD);

    const float diag_q = __fsqrt_rn(fa(fa(fm(bwq, bwq), fm(bhq, bhq)), fm(bdq, bdq)));
    const float diag_k = __fsqrt_rn(fa(fa(fm(bwk, bwk), fm(bhk, bhk)), fm(bdk, bdk)));
    const float maxdiag = fmaxf(diag_q, diag_k);

    // Candidate windows (widened; fast divides OK — exact predicate filters inside)
    const float r  = 0.5f * maxdiag;
    const float hx = __fdividef(r, bwk) + 0.02f;
    const float hy = __fdividef(r, bhk) + 0.02f;
    const float hz = __fdividef(r, bdk) + 0.02f;

    const int ix = p & 15, iy = (p >> 4) & 15, iz = p >> 8;
    const float cxv = fa(fm((float)ix + 0.5f, bwq), x0q);
    const float cyv = fa(fm((float)iy + 0.5f, bhq), y0q);
    const float czv = fa(fm((float)iz + 0.5f, bdq), z0q);

    const float txc = __fdividef(cxv - x0k, bwk) - 0.5f;
    const float tyc = __fdividef(cyv - y0k, bhk) - 0.5f;
    const float tzc = __fdividef(czv - z0k, bdk) - 0.5f;
    const int jxlo = max(0, (int)ceilf(txc - hx));
    const int jxhi = min(WW - 1, (int)floorf(txc + hx));
    const int jylo = max(0, (int)ceilf(tyc - hy));
    const int jyhi = min(HH - 1, (int)floorf(tyc + hy));
    const int jzlo = max(0, (int)ceilf(tzc - hz));
    const int jzhi = min(DD - 1, (int)floorf(tzc + hz));

    const int base16 = (n * PP + p) * 8;
    int nr = 0, cnt = 0;

    for (int jz = jzlo; jz <= jzhi; jz++) {
        const float dz  = fs(czv, fa(fm((float)jz + 0.5f, bdk), z0k));
        const float dz2 = fm(dz, dz);
        for (int jy = jylo; jy <= jyhi; jy++) {
            const float dy  = fs(cyv, fa(fm((float)jy + 0.5f, bhk), y0k));
            const float dy2 = fm(dy, dy);
            int first = -1, last = -2;
            for (int jx = jxlo; jx <= jxhi; jx++) {
                const float dx = fs(cxv, fa(fm((float)jx + 0.5f, bwk), x0k));
                const float s2 = fa(fa(fm(dx, dx), dy2), dz2);
                // exact reference predicate: sqrt then divide then compare
                if (__fdiv_rn(__fsqrt_rn(s2), maxdiag) < 0.5f) {
                    if (first < 0) first = jx;
                    last = jx;
                }
            }
            if (first >= 0) {
                const int len = last - first + 1;   // <=3 (x-passing set is an interval)
                cnt += len;
                nr++;
                const int ebase = ((jz << 4) + jy) * EW + first;  // E-array index
                g_runs16[base16 + nr] = (unsigned short)(ebase | (len << 12));
            }
        }
    }
    g_runs16[base16] = (unsigned short)nr;
    return cnt;
}

// ---------------- Fused kernel --------------------------------------------------------
__global__ void __launch_bounds__(256, 4) pixpro_fused(
    const float* __restrict__ q, const float* __restrict__ k,
    const float* __restrict__ cq, const float* __restrict__ ck,
    float* __restrict__ out)
{
    const int bx  = blockIdx.x;
    const int tid = threadIdx.x;
    const int n   = bx >> 6;           // 64 blocks per batch
    const int c0  = (bx & 63) << 2;    // first of 4 channels

    // E: per-row exclusive prefix sums, 4 channels interleaved per slot.
    // slot idx = row*17 + j  (j=0..16); float4 per slot. 128*17*16B = 34.8 KB.
    __shared__ float E[NROW * EW * 4];
    __shared__ float s_wred[8][G];
    __shared__ int   s_elect;
    __shared__ float s_loss[NB];

    // Phase 0a: mask duty — warp 0, one voxel per lane (32 voxels per block)
    if (tid < 32) {
        const int p = ((bx & 63) << 5) + tid;
        int cnt = mask_voxel(n, p, cq, ck);
        #pragma unroll
        for (int off = 16; off > 0; off >>= 1)
            cnt += __shfl_down_sync(0xFFFFFFFFu, cnt, off);
        __syncwarp();
        if (tid == 0) {
            atomicAdd(&g_cnt[n], cnt);
            __threadfence();
            atomicAdd(&g_mask_flag[n], 1);
        }
    }

    // Phase 0b: build E (warps 1..7, concurrent with warp 0's mask duty).
    // 256 tasks = (row 0..127) x (channel-half 0..1); task t: row=t&127, hf=t>>7.
    const size_t kbase = (size_t)(n * CH + c0) * PP;
    if (tid >= 32) {
        for (int task = tid - 32; task < 256; task += 224) {
            const int r  = task & 127;
            const int hf = task >> 7;                 // channels 2hf, 2hf+1
            const float4* __restrict__ k0 =
                reinterpret_cast<const float4*>(k + kbase + (size_t)(2 * hf) * PP + r * 16);
            const float4* __restrict__ k1 =
                reinterpret_cast<const float4*>(k + kbase + (size_t)(2 * hf + 1) * PP + r * 16);
            const float4 a0 = __ldcs(k0),     a1 = __ldcs(k0 + 1);
            const float4 a2 = __ldcs(k0 + 2), a3 = __ldcs(k0 + 3);
            const float4 b0 = __ldcs(k1),     b1 = __ldcs(k1 + 1);
            const float4 b2 = __ldcs(k1 + 2), b3 = __ldcs(k1 + 3);

            float2* d = reinterpret_cast<float2*>(&E[(r * EW) * 4 + 2 * hf]);
            float s0 = 0.f, s1 = 0.f;
            // E[j] = sum_{x<j} k[x]; store then accumulate, 17 slots
            d[0]  = make_float2(s0, s1); s0 += a0.x; s1 += b0.x;
            d[2]  = make_float2(s0, s1); s0 += a0.y; s1 += b0.y;
            d[4]  = make_float2(s0, s1); s0 += a0.z; s1 += b0.z;
            d[6]  = make_float2(s0, s1); s0 += a0.w; s1 += b0.w;
            d[8]  = make_float2(s0, s1); s0 += a1.x; s1 += b1.x;
            d[10] = make_float2(s0, s1); s0 += a1.y; s1 += b1.y;
            d[12] = make_float2(s0, s1); s0 += a1.z; s1 += b1.z;
            d[14] = make_float2(s0, s1); s0 += a1.w; s1 += b1.w;
            d[16] = make_float2(s0, s1); s0 += a2.x; s1 += b2.x;
            d[18] = make_float2(s0, s1); s0 += a2.y; s1 += b2.y;
            d[20] = make_float2(s0, s1); s0 += a2.z; s1 += b2.z;
            d[22] = make_float2(s0, s1); s0 += a2.w; s1 += b2.w;
            d[24] = make_float2(s0, s1); s0 += a3.x; s1 += b3.x;
            d[26] = make_float2(s0, s1); s0 += a3.y; s1 += b3.y;
            d[28] = make_float2(s0, s1); s0 += a3.z; s1 += b3.z;
            d[30] = make_float2(s0, s1); s0 += a3.w; s1 += b3.w;
            d[32] = make_float2(s0, s1);
        }
    }

    // Phase 1: wait for this batch's 64 mask chunks (512 blocks single-wave resident:
    // launch_bounds(256,4) -> capacity >=592; publishers publish before spinning)
    if (tid == 0) {
        while (*(volatile int*)&g_mask_flag[n] < 64) __nanosleep(32);
        __threadfence();
    }
    __syncthreads();   // E complete + mask visible

    // Phase 2: masked dot for 4 channels; thread owns voxels p = tid + 256*j.
    // Per run: sum = E[base+len] - E[base]  (2 LDS.128 for all 4 channels).
    const uint4* __restrict__ rp =
        reinterpret_cast<const uint4*>(g_runs16) + (size_t)n * PP;
    const float* __restrict__ qp = q + (size_t)(n * CH + c0) * PP;
    const float4* __restrict__ E4 = reinterpret_cast<const float4*>(E);

    float l0 = 0.f, l1 = 0.f, l2 = 0.f, l3 = 0.f;
    #pragma unroll
    for (int j = 0; j < 8; j++) {
        const int p = tid + (j << 8);
        const uint4 h  = __ldcg(rp + p);
        const float q0 = __ldcs(qp + p);
        const float q1 = __ldcs(qp + PP + p);
        const float q2 = __ldcs(qp + 2 * PP + p);
        const float q3 = __ldcs(qp + 3 * PP + p);
        const int nr = (int)(h.x & 0xFFFFu);
        float a0 = 0.f, a1 = 0.f, a2 = 0.f, a3 = 0.f;
        #pragma unroll
        for (int s = 1; s <= 6; s++) {
            const unsigned w = (s < 2) ? h.x : ((s < 4) ? h.y : ((s < 6) ? h.z : h.w));
            const unsigned run = (s & 1) ? (w >> 16) : (w & 0xFFFFu);
            const int base = (int)(run & 0xFFFu);
            const int len  = (int)((run >> 12) & 0x3u);
            if (s <= nr) {
                const float4 e1 = E4[base + len];
                const float4 e0 = E4[base];
                a0 += e1.x - e0.x;
                a1 += e1.y - e0.y;
                a2 += e1.z - e0.z;
                a3 += e1.w - e0.w;
            }
        }
        l0 = fmaf(q0, a0, l0);
        l1 = fmaf(q1, a1, l1);
        l2 = fmaf(q2, a2, l2);
        l3 = fmaf(q3, a3, l3);
    }

    // Per-channel deterministic reduction (warp shuffle + fixed-order cross-warp)
    #pragma unroll
    for (int off = 16; off > 0; off >>= 1) {
        l0 += __shfl_down_sync(0xFFFFFFFFu, l0, off);
        l1 += __shfl_down_sync(0xFFFFFFFFu, l1, off);
        l2 += __shfl_down_sync(0xFFFFFFFFu, l2, off);
        l3 += __shfl_down_sync(0xFFFFFFFFu, l3, off);
    }
    if ((tid & 31) == 0) {
        const int w = tid >> 5;
        s_wred[w][0] = l0; s_wred[w][1] = l1; s_wred[w][2] = l2; s_wred[w][3] = l3;
    }
    __syncthreads();

    // tid 0 writes all 4 partials (so its threadfence orders them), then tickets
    if (tid == 0) {
        #pragma unroll
        for (int g = 0; g < G; g++) {
            float s = 0.f;
            #pragma unroll
            for (int w = 0; w < 8; w++) s += s_wred[w][g];
            g_partials[n * CH + c0 + g] = s;
        }
        __threadfence();
        s_elect = (atomicAdd(&g_done, 1) == NBLK - 1) ? 1 : 0;
    }
    __syncthreads();

    // Phase 3: last-done block finalizes (fixed-order, deterministic)
    if (s_elect) {
        const int w    = tid >> 5;   // batch index
        const int lane = tid & 31;
        float s = 0.f;
        #pragma unroll
        for (int j = 0; j < 8; j++)
            s += __ldcg(&g_partials[w * CH + j * 32 + lane]);
        #pragma unroll
        for (int off = 16; off > 0; off >>= 1)
            s += __shfl_down_sync(0xFFFFFFFFu, s, off);
        if (lane == 0)
            s_loss[w] = s / ((float)__ldcg(&g_cnt[w]) + 1e-6f);
        __syncthreads();
        if (tid == 0) {
            float m = 0.f;
            #pragma unroll
            for (int i = 0; i < NB; i++) m += s_loss[i];
            out[0] = -2.0f * (m * (1.0f / (float)NB));
            // self-reset for next graph replay (all blocks already ticketed)
            #pragma unroll
            for (int i = 0; i < NB; i++) { g_mask_flag[i] = 0; g_cnt[i] = 0; }
            g_done = 0;
        }
    }
}

extern "C" void kernel_launch(void* const* d_in, const int* in_sizes, int n_in,
                              void* d_out, int out_size)
{
    const float* q  = (const float*)d_in[0];
    const float* k  = (const float*)d_in[1];
    const float* cq = (const float*)d_in[2];
    const float* ck = (const float*)d_in[3];
    float* out = (float*)d_out;

    pixpro_fused<<<NBLK, 256>>>(q, k, cq, ck, out);
}

// round 11
// speedup vs baseline: 1.0987x; 1.0152x over previous
#include <cuda_runtime.h>

// Problem constants (fixed by setup_inputs)
#define NB 8
#define CH 256
#define DD 8
#define HH 16
#define WW 16
#define PP 2048            // DD*HH*WW
#define G  4               // channels per block
#define NBLK (NB * (CH / G))   // 512 blocks, 64 per batch
#define NROW (DD * HH)     // 128 k-rows (z,y), 16 x-values each
#define EW 17              // exclusive-prefix width per row

// Scratch (no allocations allowed)
__device__ float g_partials[NB * CH];
__device__ int   g_cnt[NB];        // per-batch mask counts (single writer each)
__device__ int   g_done;           // completion ticket; reset by finalizer

// Non-contractable f32 ops (reference-matching center arithmetic)
__device__ __forceinline__ float fm(float a, float b) { return __fmul_rn(a, b); }
__device__ __forceinline__ float fa(float a, float b) { return __fadd_rn(a, b); }
__device__ __forceinline__ float fs(float a, float b) { return __fsub_rn(a, b); }

// ---------------- Fused kernel: fully independent blocks ----------------------------
__global__ void __launch_bounds__(256, 4) pixpro_fused(
    const float* __restrict__ q, const float* __restrict__ k,
    const float* __restrict__ cq, const float* __restrict__ ck,
    float* __restrict__ out)
{
    const int bx  = blockIdx.x;
    const int tid = threadIdx.x;
    const int n   = bx >> 6;           // 64 blocks per batch
    const int c0  = (bx & 63) << 2;    // first of 4 channels

    // E: per-row exclusive prefix sums, 4 channels interleaved: float4 per slot
    // slot = row*17 + j. 128*17*16B = 34.8 KB.
    __shared__ float E[NROW * EW * 4];
    __shared__ float s_wred[8][G];
    __shared__ int   s_credN[8];
    __shared__ int   s_elect;
    __shared__ float s_loss[NB];

    // ---- Geometry (exact reference arithmetic for centers / diag) ----
    const float x0q = cq[n * 6 + 0], y0q = cq[n * 6 + 1], z0q = cq[n * 6 + 2];
    const float x1q = cq[n * 6 + 3], y1q = cq[n * 6 + 4], z1q = cq[n * 6 + 5];
    const float x0k = ck[n * 6 + 0], y0k = ck[n * 6 + 1], z0k = ck[n * 6 + 2];
    const float x1k = ck[n * 6 + 3], y1k = ck[n * 6 + 4], z1k = ck[n * 6 + 5];

    const float bwq = __fdiv_rn(fs(x1q, x0q), (float)WW);
    const float bhq = __fdiv_rn(fs(y1q, y0q), (float)HH);
    const float bdq = __fdiv_rn(fs(z1q, z0q), (float)DD);
    const float bwk = __fdiv_rn(fs(x1k, x0k), (float)WW);
    const float bhk = __fdiv_rn(fs(y1k, y0k), (float)HH);
    const float bdk = __fdiv_rn(fs(z1k, z0k), (float)DD);

    const float diag_q = __fsqrt_rn(fa(fa(fm(bwq, bwq), fm(bhq, bhq)), fm(bdq, bdq)));
    const float diag_k = __fsqrt_rn(fa(fa(fm(bwk, bwk), fm(bhk, bhk)), fm(bdk, bdk)));
    const float maxdiag = fmaxf(diag_q, diag_k);
    const float r       = 0.5f * maxdiag;
    const float thresh2 = r * r;                 // squared predicate threshold

    const float ibwk = 1.0f / bwk;
    const float ibhk = 1.0f / bhk;
    const float ibdk = 1.0f / bdk;

    // Per-thread invariants: ix, iy fixed across the iz loop (p = tid + 256*iz)
    const int   ix  = tid & 15;
    const int   iy  = (tid >> 4) & 15;
    const float cxv = fa(fm((float)ix + 0.5f, bwq), x0q);
    const float cyv = fa(fm((float)iy + 0.5f, bhq), y0q);
    const float txc = (cxv - x0k) * ibwk - 0.5f;  // x index-space center
    const float tyc = (cyv - y0k) * ibhk - 0.5f;

    // ---- Build E: 256 tasks = (row 0..127) x (channel-half 0..1), one per thread ----
    const size_t kbase = (size_t)(n * CH + c0) * PP;
    {
        const int rrow = tid & 127;
        const int hf   = tid >> 7;                // channels 2hf, 2hf+1
        const float4* __restrict__ k0 =
            reinterpret_cast<const float4*>(k + kbase + (size_t)(2 * hf) * PP + rrow * 16);
        const float4* __restrict__ k1 =
            reinterpret_cast<const float4*>(k + kbase + (size_t)(2 * hf + 1) * PP + rrow * 16);
        const float4 a0 = __ldcs(k0),     a1 = __ldcs(k0 + 1);
        const float4 a2 = __ldcs(k0 + 2), a3 = __ldcs(k0 + 3);
        const float4 b0 = __ldcs(k1),     b1 = __ldcs(k1 + 1);
        const float4 b2 = __ldcs(k1 + 2), b3 = __ldcs(k1 + 3);

        float2* d = reinterpret_cast<float2*>(&E[(rrow * EW) * 4 + 2 * hf]);
        float s0 = 0.f, s1 = 0.f;
        d[0]  = make_float2(s0, s1); s0 += a0.x; s1 += b0.x;
        d[2]  = make_float2(s0, s1); s0 += a0.y; s1 += b0.y;
        d[4]  = make_float2(s0, s1); s0 += a0.z; s1 += b0.z;
        d[6]  = make_float2(s0, s1); s0 += a0.w; s1 += b0.w;
        d[8]  = make_float2(s0, s1); s0 += a1.x; s1 += b1.x;
        d[10] = make_float2(s0, s1); s0 += a1.y; s1 += b1.y;
        d[12] = make_float2(s0, s1); s0 += a1.z; s1 += b1.z;
        d[14] = make_float2(s0, s1); s0 += a1.w; s1 += b1.w;
        d[16] = make_float2(s0, s1); s0 += a2.x; s1 += b2.x;
        d[18] = make_float2(s0, s1); s0 += a2.y; s1 += b2.y;
        d[20] = make_float2(s0, s1); s0 += a2.z; s1 += b2.z;
        d[22] = make_float2(s0, s1); s0 += a2.w; s1 += b2.w;
        d[24] = make_float2(s0, s1); s0 += a3.x; s1 += b3.x;
        d[26] = make_float2(s0, s1); s0 += a3.y; s1 += b3.y;
        d[28] = make_float2(s0, s1); s0 += a3.z; s1 += b3.z;
        d[30] = make_float2(s0, s1); s0 += a3.w; s1 += b3.w;
        d[32] = make_float2(s0, s1);
    }
    __syncthreads();

    // ---- Masked dot: windows computed analytically in-loop, no records ----
    const float* __restrict__ qp = q + (size_t)(n * CH + c0) * PP;
    const float4* __restrict__ E4 = reinterpret_cast<const float4*>(E);

    float l0 = 0.f, l1 = 0.f, l2 = 0.f, l3 = 0.f;
    int   cnt = 0;

    #pragma unroll
    for (int iz = 0; iz < DD; iz++) {
        const int p = tid + (iz << 8);
        const float q0 = __ldcs(qp + p);
        const float q1 = __ldcs(qp + PP + p);
        const float q2 = __ldcs(qp + 2 * PP + p);
        const float q3 = __ldcs(qp + 3 * PP + p);

        const float czv = fa(fm((float)iz + 0.5f, bdq), z0q);
        const float tzc = (czv - z0k) * ibdk - 0.5f;
        const float rz  = r * ibdk;
        const int jzlo  = max(0, (int)ceilf(tzc - rz - 0.01f));
        const int jzhi  = min(DD - 1, (int)floorf(tzc + rz + 0.01f));

        float a0 = 0.f, a1 = 0.f, a2 = 0.f, a3 = 0.f;
        for (int jz = jzlo; jz <= jzhi; jz++) {
            const float ckzv = fa(fm((float)jz + 0.5f, bdk), z0k);
            const float dz   = fs(czv, ckzv);
            const float remz = thresh2 - fm(dz, dz);
            if (remz <= 0.f) continue;
            const float sqy = __fsqrt_rn(remz);
            const float ry  = sqy * ibhk;
            const int jylo  = max(0, (int)ceilf(tyc - ry - 0.01f));
            const int jyhi  = min(HH - 1, (int)floorf(tyc + ry + 0.01f));
            for (int jy = jylo; jy <= jyhi; jy++) {
                const float ckyv = fa(fm((float)jy + 0.5f, bhk), y0k);
                const float dy   = fs(cyv, ckyv);
                const float rem2 = remz - fm(dy, dy);
                if (rem2 <= 0.f) continue;
                const float sq = __fsqrt_rn(rem2);
                const float rx = sq * ibwk;
                const int first = max(0, (int)ceilf(txc - rx));
                const int last  = min(WW - 1, (int)floorf(txc + rx));
                if (last >= first) {
                    const int len = last - first + 1;
                    cnt += len;
                    const int eb = ((jz << 4) + jy) * EW + first;
                    const float4 e1 = E4[eb + len];
                    const float4 e0 = E4[eb];
                    a0 += e1.x - e0.x;
                    a1 += e1.y - e0.y;
                    a2 += e1.z - e0.z;
                    a3 += e1.w - e0.w;
                }
            }
        }
        l0 = fmaf(q0, a0, l0);
        l1 = fmaf(q1, a1, l1);
        l2 = fmaf(q2, a2, l2);
        l3 = fmaf(q3, a3, l3);
    }

    // ---- Per-channel deterministic reduction ----
    #pragma unroll
    for (int off = 16; off > 0; off >>= 1) {
        l0  += __shfl_down_sync(0xFFFFFFFFu, l0, off);
        l1  += __shfl_down_sync(0xFFFFFFFFu, l1, off);
        l2  += __shfl_down_sync(0xFFFFFFFFu, l2, off);
        l3  += __shfl_down_sync(0xFFFFFFFFu, l3, off);
        cnt += __shfl_down_sync(0xFFFFFFFFu, cnt, off);
    }
    if ((tid & 31) == 0) {
        const int w = tid >> 5;
        s_wred[w][0] = l0; s_wred[w][1] = l1; s_wred[w][2] = l2; s_wred[w][3] = l3;
        s_credN[w]   = cnt;
    }
    __syncthreads();

    // tid 0 publishes partials (+ count if first block of batch), then tickets
    if (tid == 0) {
        #pragma unroll
        for (int g = 0; g < G; g++) {
            float s = 0.f;
            #pragma unroll
            for (int w = 0; w < 8; w++) s += s_wred[w][g];
            g_partials[n * CH + c0 + g] = s;
        }
        if ((bx & 63) == 0) {
            int c = 0;
            #pragma unroll
            for (int w = 0; w < 8; w++) c += s_credN[w];
            g_cnt[n] = c;       // single writer per batch, deterministic
        }
        __threadfence();
        s_elect = (atomicAdd(&g_done, 1) == NBLK - 1) ? 1 : 0;
    }
    __syncthreads();

    // ---- Last-done block finalizes (fixed-order, deterministic) ----
    if (s_elect) {
        const int w    = tid >> 5;   // batch index
        const int lane = tid & 31;
        float s = 0.f;
        #pragma unroll
        for (int j = 0; j < 8; j++)
            s += __ldcg(&g_partials[w * CH + j * 32 + lane]);
        #pragma unroll
        for (int off = 16; off > 0; off >>= 1)
            s += __shfl_down_sync(0xFFFFFFFFu, s, off);
        if (lane == 0)
            s_loss[w] = s / ((float)__ldcg(&g_cnt[w]) + 1e-6f);
        __syncthreads();
        if (tid == 0) {
            float m = 0.f;
            #pragma unroll
            for (int i = 0; i < NB; i++) m += s_loss[i];
            out[0] = -2.0f * (m * (1.0f / (float)NB));
            g_done = 0;          // self-reset for next graph replay
        }
    }
}

extern "C" void kernel_launch(void* const* d_in, const int* in_sizes, int n_in,
                              void* d_out, int out_size)
{
    const float* q  = (const float*)d_in[0];
    const float* k  = (const float*)d_in[1];
    const float* cq = (const float*)d_in[2];
    const float* ck = (const float*)d_in[3];
    float* out = (float*)d_out;

    pixpro_fused<<<NBLK, 256>>>(q, k, cq, ck, out);
}

// round 12
// speedup vs baseline: 1.1265x; 1.0253x over previous
#include <cuda_runtime.h>

// Problem constants (fixed by setup_inputs)
#define NB 8
#define CH 256
#define DD 8
#define HH 16
#define WW 16
#define PP 2048            // DD*HH*WW
#define G  4               // channels per block
#define NBLK (NB * (CH / G))   // 512 blocks, 64 per batch

// Scratch (no allocations allowed)
__device__ float g_partials[NB * CH];
__device__ int   g_cnt[NB];        // per-batch mask counts (int atomics: deterministic)
// Per-voxel run records: 8 x u16: slot0=nruns; slots1..6: bits[0:11)=base, [11:13)=len(1..3)
__device__ __align__(16) unsigned short g_runs16[NB * PP * 8];
__device__ int g_done;             // completion ticket; reset by finalizer

// Non-contractable f32 ops: mask predicate must be bit-identical to plain IEEE f32
__device__ __forceinline__ float fm(float a, float b) { return __fmul_rn(a, b); }
__device__ __forceinline__ float fa(float a, float b) { return __fadd_rn(a, b); }
__device__ __forceinline__ float fs(float a, float b) { return __fsub_rn(a, b); }

// ---------------- Kernel A: mask records, one voxel per thread ----------------------
__global__ void __launch_bounds__(128) pixpro_mask(
    const float* __restrict__ cq, const float* __restrict__ ck)
{
    const int gidx = blockIdx.x * 128 + threadIdx.x;   // 0 .. NB*PP-1
    const int n = gidx >> 11;
    const int p = gidx & (PP - 1);

    const float x0q = cq[n * 6 + 0], y0q = cq[n * 6 + 1], z0q = cq[n * 6 + 2];
    const float x1q = cq[n * 6 + 3], y1q = cq[n * 6 + 4], z1q = cq[n * 6 + 5];
    const float x0k = ck[n * 6 + 0], y0k = ck[n * 6 + 1], z0k = ck[n * 6 + 2];
    const float x1k = ck[n * 6 + 3], y1k = ck[n * 6 + 4], z1k = ck[n * 6 + 5];

    const float bwq = __fdiv_rn(fs(x1q, x0q), (float)WW);
    const float bhq = __fdiv_rn(fs(y1q, y0q), (float)HH);
    const float bdq = __fdiv_rn(fs(z1q, z0q), (float)DD);
    const float bwk = __fdiv_rn(fs(x1k, x0k), (float)WW);
    const float bhk = __fdiv_rn(fs(y1k, y0k), (float)HH);
    const float bdk = __fdiv_rn(fs(z1k, z0k), (float)DD);

    const float diag_q = __fsqrt_rn(fa(fa(fm(bwq, bwq), fm(bhq, bhq)), fm(bdq, bdq)));
    const float diag_k = __fsqrt_rn(fa(fa(fm(bwk, bwk), fm(bhk, bhk)), fm(bdk, bdk)));
    const float maxdiag = fmaxf(diag_q, diag_k);

    // Candidate windows (widened; fast divides OK — exact predicate filters inside)
    const float r  = 0.5f * maxdiag;
    const float hx = __fdividef(r, bwk) + 0.02f;
    const float hy = __fdividef(r, bhk) + 0.02f;
    const float hz = __fdividef(r, bdk) + 0.02f;

    const int ix = p & 15, iy = (p >> 4) & 15, iz = p >> 8;
    const float cxv = fa(fm((float)ix + 0.5f, bwq), x0q);
    const float cyv = fa(fm((float)iy + 0.5f, bhq), y0q);
    const float czv = fa(fm((float)iz + 0.5f, bdq), z0q);

    const float txc = __fdividef(cxv - x0k, bwk) - 0.5f;
    const float tyc = __fdividef(cyv - y0k, bhk) - 0.5f;
    const float tzc = __fdividef(czv - z0k, bdk) - 0.5f;
    const int jxlo = max(0, (int)ceilf(txc - hx));
    const int jxhi = min(WW - 1, (int)floorf(txc + hx));
    const int jylo = max(0, (int)ceilf(tyc - hy));
    const int jyhi = min(HH - 1, (int)floorf(tyc + hy));
    const int jzlo = max(0, (int)ceilf(tzc - hz));
    const int jzhi = min(DD - 1, (int)floorf(tzc + hz));

    const int base16 = gidx * 8;
    int nr = 0, cnt = 0;

    for (int jz = jzlo; jz <= jzhi; jz++) {
        const float dz  = fs(czv, fa(fm((float)jz + 0.5f, bdk), z0k));
        const float dz2 = fm(dz, dz);
        for (int jy = jylo; jy <= jyhi; jy++) {
            const float dy  = fs(cyv, fa(fm((float)jy + 0.5f, bhk), y0k));
            const float dy2 = fm(dy, dy);
            int first = -1, last = -2;
            for (int jx = jxlo; jx <= jxhi; jx++) {
                const float dx = fs(cxv, fa(fm((float)jx + 0.5f, bwk), x0k));
                const float s2 = fa(fa(fm(dx, dx), dy2), dz2);
                // exact reference predicate: sqrt then divide then compare
                if (__fdiv_rn(__fsqrt_rn(s2), maxdiag) < 0.5f) {
                    if (first < 0) first = jx;
                    last = jx;
                }
            }
            if (first >= 0) {
                const int len = last - first + 1;   // <=3 (x-passing set is an interval)
                cnt += len;
                nr++;
                g_runs16[base16 + nr] =
                    (unsigned short)(((jz << 8) + (jy << 4) + first) | (len << 11));
            }
        }
    }
    g_runs16[base16] = (unsigned short)nr;

    // warp-reduced count -> one atomic per warp (deterministic: int)
    #pragma unroll
    for (int off = 16; off > 0; off >>= 1)
        cnt += __shfl_down_sync(0xFFFFFFFFu, cnt, off);
    if ((threadIdx.x & 31) == 0 && cnt) atomicAdd(&g_cnt[n], cnt);
}

// ---------------- Kernel B: grouped dot + finalize (no mask, no spin) ---------------
__global__ void __launch_bounds__(256, 4) pixpro_dot(
    const float* __restrict__ q, const float* __restrict__ k,
    float* __restrict__ out)
{
    const int bx  = blockIdx.x;
    const int tid = threadIdx.x;
    const int n   = bx >> 6;           // 64 blocks per batch
    const int c0  = (bx & 63) << 2;    // first of 4 channels

    __shared__ float4 ks4[PP];         // 32 KB: 4 channels interleaved per voxel
    __shared__ float  s_wred[8][G];
    __shared__ int    s_elect;
    __shared__ float  s_loss[NB];

    // Stage k: all 8 warps, 4 channels -> float4-interleaved smem
    const size_t kbase = (size_t)(n * CH + c0) * PP;
    #pragma unroll
    for (int j = 0; j < 8; j++) {
        const int i = tid + (j << 8);
        float4 v;
        v.x = __ldcs(k + kbase + i);
        v.y = __ldcs(k + kbase + PP + i);
        v.z = __ldcs(k + kbase + 2 * PP + i);
        v.w = __ldcs(k + kbase + 3 * PP + i);
        ks4[i] = v;
    }
    __syncthreads();

    // Masked dot for 4 channels; thread owns voxels p = tid + 256*j
    const uint4* __restrict__ rp =
        reinterpret_cast<const uint4*>(g_runs16) + (size_t)n * PP;
    const float* __restrict__ qp = q + (size_t)(n * CH + c0) * PP;

    float l0 = 0.f, l1 = 0.f, l2 = 0.f, l3 = 0.f;
    #pragma unroll
    for (int j = 0; j < 8; j++) {
        const int p = tid + (j << 8);
        const uint4 h  = __ldcg(rp + p);    // records live in L2 (256 KB total)
        const float q0 = __ldcs(qp + p);
        const float q1 = __ldcs(qp + PP + p);
        const float q2 = __ldcs(qp + 2 * PP + p);
        const float q3 = __ldcs(qp + 3 * PP + p);
        const int nr = (int)(h.x & 0xFFFFu);
        float a0 = 0.f, a1 = 0.f, a2 = 0.f, a3 = 0.f;
        #pragma unroll
        for (int s = 1; s <= 6; s++) {
            const unsigned w = (s < 2) ? h.x : ((s < 4) ? h.y : ((s < 6) ? h.z : h.w));
            const unsigned run = (s & 1) ? (w >> 16) : (w & 0xFFFFu);
            const int base = (int)(run & 0x7FFu);
            const int len  = (int)((run >> 11) & 0x3u);
            if (s <= nr) {
                float4 v = ks4[base];
                a0 += v.x; a1 += v.y; a2 += v.z; a3 += v.w;
                if (len > 1) { float4 u = ks4[base + 1]; a0 += u.x; a1 += u.y; a2 += u.z; a3 += u.w; }
                if (len > 2) { float4 u = ks4[base + 2]; a0 += u.x; a1 += u.y; a2 += u.z; a3 += u.w; }
            }
        }
        l0 = fmaf(q0, a0, l0);
        l1 = fmaf(q1, a1, l1);
        l2 = fmaf(q2, a2, l2);
        l3 = fmaf(q3, a3, l3);
    }

    // Per-channel deterministic reduction (warp shuffle + fixed-order cross-warp)
    #pragma unroll
    for (int off = 16; off > 0; off >>= 1) {
        l0 += __shfl_down_sync(0xFFFFFFFFu, l0, off);
        l1 += __shfl_down_sync(0xFFFFFFFFu, l1, off);
        l2 += __shfl_down_sync(0xFFFFFFFFu, l2, off);
        l3 += __shfl_down_sync(0xFFFFFFFFu, l3, off);
    }
    if ((tid & 31) == 0) {
        const int w = tid >> 5;
        s_wred[w][0] = l0; s_wred[w][1] = l1; s_wred[w][2] = l2; s_wred[w][3] = l3;
    }
    __syncthreads();

    // tid 0 writes all 4 partials (so its threadfence orders them), then tickets
    if (tid == 0) {
        #pragma unroll
        for (int g = 0; g < G; g++) {
            float s = 0.f;
            #pragma unroll
            for (int w = 0; w < 8; w++) s += s_wred[w][g];
            g_partials[n * CH + c0 + g] = s;
        }
        __threadfence();
        s_elect = (atomicAdd(&g_done, 1) == NBLK - 1) ? 1 : 0;
    }
    __syncthreads();

    // Last-done block finalizes (fixed-order, deterministic)
    if (s_elect) {
        const int w    = tid >> 5;   // batch index
        const int lane = tid & 31;
        float s = 0.f;
        #pragma unroll
        for (int j = 0; j < 8; j++)
            s += __ldcg(&g_partials[w * CH + j * 32 + lane]);
        #pragma unroll
        for (int off = 16; off > 0; off >>= 1)
            s += __shfl_down_sync(0xFFFFFFFFu, s, off);
        if (lane == 0) {
            s_loss[w] = s / ((float)__ldcg(&g_cnt[w]) + 1e-6f);
            g_cnt[w] = 0;        // reset for next graph replay (A rebuilds it)
        }
        __syncthreads();
        if (tid == 0) {
            float m = 0.f;
            #pragma unroll
            for (int i = 0; i < NB; i++) m += s_loss[i];
            out[0] = -2.0f * (m * (1.0f / (float)NB));
            g_done = 0;          // self-reset for next graph replay
        }
    }
}

extern "C" void kernel_launch(void* const* d_in, const int* in_sizes, int n_in,
                              void* d_out, int out_size)
{
    const float* q  = (const float*)d_in[0];
    const float* k  = (const float*)d_in[1];
    const float* cq = (const float*)d_in[2];
    const float* ck = (const float*)d_in[3];
    float* out = (float*)d_out;

    pixpro_mask<<<NB * PP / 128, 128>>>(cq, ck);
    pixpro_dot<<<NBLK, 256>>>(q, k, out);
}

// round 13
// speedup vs baseline: 1.2505x; 1.1102x over previous
#include <cuda_runtime.h>

// Problem constants (fixed by setup_inputs)
#define NB 8
#define CH 256
#define DD 8
#define HH 16
#define WW 16
#define PP 2048            // DD*HH*WW
#define G  4               // channels per block
#define NBLK (NB * (CH / G))   // 512 blocks, 64 per batch

// Scratch (no allocations allowed)
__device__ float g_partials[NB * CH];
__device__ int   g_cnt[NB];        // per-batch mask counts (int atomics: deterministic)
// Per-voxel run records: 8 x u16: slot0=nruns; slots1..6: bits[0:11)=base, [11:13)=len(1..3)
__device__ __align__(16) unsigned short g_runs16[NB * PP * 8];
__device__ int g_done;             // completion ticket; reset by finalizer

// Non-contractable f32 ops (reference-matching center arithmetic)
__device__ __forceinline__ float fm(float a, float b) { return __fmul_rn(a, b); }
__device__ __forceinline__ float fa(float a, float b) { return __fadd_rn(a, b); }
__device__ __forceinline__ float fs(float a, float b) { return __fsub_rn(a, b); }

// ---------------- Kernel A: mask records, one voxel per thread ----------------------
// Predicate: s2 < (0.5*maxdiag)^2  (monotone-equivalent to sqrt(s2)/maxdiag < 0.5;
// no MUFU in the inner loop).
__global__ void __launch_bounds__(256) pixpro_mask(
    const float* __restrict__ cq, const float* __restrict__ ck)
{
    const int gidx = blockIdx.x * 256 + threadIdx.x;   // 0 .. NB*PP-1
    const int n = gidx >> 11;
    const int p = gidx & (PP - 1);

    const float x0q = cq[n * 6 + 0], y0q = cq[n * 6 + 1], z0q = cq[n * 6 + 2];
    const float x1q = cq[n * 6 + 3], y1q = cq[n * 6 + 4], z1q = cq[n * 6 + 5];
    const float x0k = ck[n * 6 + 0], y0k = ck[n * 6 + 1], z0k = ck[n * 6 + 2];
    const float x1k = ck[n * 6 + 3], y1k = ck[n * 6 + 4], z1k = ck[n * 6 + 5];

    const float bwq = __fdiv_rn(fs(x1q, x0q), (float)WW);
    const float bhq = __fdiv_rn(fs(y1q, y0q), (float)HH);
    const float bdq = __fdiv_rn(fs(z1q, z0q), (float)DD);
    const float bwk = __fdiv_rn(fs(x1k, x0k), (float)WW);
    const float bhk = __fdiv_rn(fs(y1k, y0k), (float)HH);
    const float bdk = __fdiv_rn(fs(z1k, z0k), (float)DD);

    const float diag_q = __fsqrt_rn(fa(fa(fm(bwq, bwq), fm(bhq, bhq)), fm(bdq, bdq)));
    const float diag_k = __fsqrt_rn(fa(fa(fm(bwk, bwk), fm(bhk, bhk)), fm(bdk, bdk)));
    const float maxdiag = fmaxf(diag_q, diag_k);

    const float r  = 0.5f * maxdiag;
    const float r2 = r * r;                         // squared threshold
    const float hx = __fdividef(r, bwk) + 0.02f;    // windows (widened; exact test inside)
    const float hy = __fdividef(r, bhk) + 0.02f;
    const float hz = __fdividef(r, bdk) + 0.02f;

    const int ix = p & 15, iy = (p >> 4) & 15, iz = p >> 8;
    const float cxv = fa(fm((float)ix + 0.5f, bwq), x0q);
    const float cyv = fa(fm((float)iy + 0.5f, bhq), y0q);
    const float czv = fa(fm((float)iz + 0.5f, bdq), z0q);

    const float txc = __fdividef(cxv - x0k, bwk) - 0.5f;
    const float tyc = __fdividef(cyv - y0k, bhk) - 0.5f;
    const float tzc = __fdividef(czv - z0k, bdk) - 0.5f;
    const int jxlo = max(0, (int)ceilf(txc - hx));
    const int jxhi = min(WW - 1, (int)floorf(txc + hx));
    const int jylo = max(0, (int)ceilf(tyc - hy));
    const int jyhi = min(HH - 1, (int)floorf(tyc + hy));
    const int jzlo = max(0, (int)ceilf(tzc - hz));
    const int jzhi = min(DD - 1, (int)floorf(tzc + hz));

    const int base16 = gidx * 8;
    int nr = 0, cnt = 0;

    for (int jz = jzlo; jz <= jzhi; jz++) {
        const float dz  = fs(czv, fa(fm((float)jz + 0.5f, bdk), z0k));
        const float dz2 = fm(dz, dz);
        for (int jy = jylo; jy <= jyhi; jy++) {
            const float dy  = fs(cyv, fa(fm((float)jy + 0.5f, bhk), y0k));
            const float dy2 = fm(dy, dy);
            int first = -1, last = -2;
            #pragma unroll 4
            for (int jx = jxlo; jx <= jxhi; jx++) {
                const float dx = fs(cxv, fa(fm((float)jx + 0.5f, bwk), x0k));
                const float s2 = fa(fa(fm(dx, dx), dy2), dz2);
                if (s2 < r2) {                     // div/sqrt-free predicate
                    if (first < 0) first = jx;
                    last = jx;
                }
            }
            if (first >= 0) {
                const int len = last - first + 1;  // <=3 (x-passing set is an interval)
                cnt += len;
                nr++;
                g_runs16[base16 + nr] =
                    (unsigned short)(((jz << 8) + (jy << 4) + first) | (len << 11));
            }
        }
    }
    g_runs16[base16] = (unsigned short)nr;

    // warp-reduced count -> one atomic per warp (deterministic: int)
    #pragma unroll
    for (int off = 16; off > 0; off >>= 1)
        cnt += __shfl_down_sync(0xFFFFFFFFu, cnt, off);
    if ((threadIdx.x & 31) == 0 && cnt) atomicAdd(&g_cnt[n], cnt);
}

// Process one voxel's record against the 4-channel smem tile
__device__ __forceinline__ void process_record(
    const uint4 h, const float4* __restrict__ ks4,
    float& a0, float& a1, float& a2, float& a3)
{
    const int nr = (int)(h.x & 0xFFFFu);
    #pragma unroll
    for (int s = 1; s <= 6; s++) {
        const unsigned w = (s < 2) ? h.x : ((s < 4) ? h.y : ((s < 6) ? h.z : h.w));
        const unsigned run = (s & 1) ? (w >> 16) : (w & 0xFFFFu);
        const int base = (int)(run & 0x7FFu);
        const int len  = (int)((run >> 11) & 0x3u);
        if (s <= nr) {
            float4 v = ks4[base];
            a0 += v.x; a1 += v.y; a2 += v.z; a3 += v.w;
            if (len > 1) { float4 u = ks4[base + 1]; a0 += u.x; a1 += u.y; a2 += u.z; a3 += u.w; }
            if (len > 2) { float4 u = ks4[base + 2]; a0 += u.x; a1 += u.y; a2 += u.z; a3 += u.w; }
        }
    }
}

// ---------------- Kernel B: grouped dot + finalize ----------------------------------
__global__ void __launch_bounds__(256, 4) pixpro_dot(
    const float* __restrict__ q, const float* __restrict__ k,
    float* __restrict__ out)
{
    const int bx  = blockIdx.x;
    const int tid = threadIdx.x;
    const int n   = bx >> 6;           // 64 blocks per batch
    const int c0  = (bx & 63) << 2;    // first of 4 channels

    __shared__ float4 ks4[PP];         // 32 KB: 4 channels interleaved per voxel
    __shared__ float  s_wred[8][G];
    __shared__ int    s_elect;
    __shared__ float  s_loss[NB];

    // Stage k: all 8 warps, 4 channels -> float4-interleaved smem
    const size_t kbase = (size_t)(n * CH + c0) * PP;
    #pragma unroll
    for (int j = 0; j < 8; j++) {
        const int i = tid + (j << 8);
        float4 v;
        v.x = __ldcs(k + kbase + i);
        v.y = __ldcs(k + kbase + PP + i);
        v.z = __ldcs(k + kbase + 2 * PP + i);
        v.w = __ldcs(k + kbase + 3 * PP + i);
        ks4[i] = v;
    }
    __syncthreads();

    // Masked dot for 4 channels, records prefetched in batches of 4 (MLP for L2 lat)
    const uint4* __restrict__ rp =
        reinterpret_cast<const uint4*>(g_runs16) + (size_t)n * PP;
    const float* __restrict__ qp = q + (size_t)(n * CH + c0) * PP;

    float l0 = 0.f, l1 = 0.f, l2 = 0.f, l3 = 0.f;
    #pragma unroll
    for (int jj = 0; jj < 2; jj++) {
        uint4 hb[4];
        #pragma unroll
        for (int t = 0; t < 4; t++)
            hb[t] = __ldcg(rp + tid + ((jj * 4 + t) << 8));

        #pragma unroll
        for (int t = 0; t < 4; t++) {
            const int p = tid + ((jj * 4 + t) << 8);
            const float q0 = __ldcs(qp + p);
            const float q1 = __ldcs(qp + PP + p);
            const float q2 = __ldcs(qp + 2 * PP + p);
            const float q3 = __ldcs(qp + 3 * PP + p);
            float a0 = 0.f, a1 = 0.f, a2 = 0.f, a3 = 0.f;
            process_record(hb[t], ks4, a0, a1, a2, a3);
            l0 = fmaf(q0, a0, l0);
            l1 = fmaf(q1, a1, l1);
            l2 = fmaf(q2, a2, l2);
            l3 = fmaf(q3, a3, l3);
        }
    }

    // Per-channel deterministic reduction (warp shuffle + fixed-order cross-warp)
    #pragma unroll
    for (int off = 16; off > 0; off >>= 1) {
        l0 += __shfl_down_sync(0xFFFFFFFFu, l0, off);
        l1 += __shfl_down_sync(0xFFFFFFFFu, l1, off);
        l2 += __shfl_down_sync(0xFFFFFFFFu, l2, off);
        l3 += __shfl_down_sync(0xFFFFFFFFu, l3, off);
    }
    if ((tid & 31) == 0) {
        const int w = tid >> 5;
        s_wred[w][0] = l0; s_wred[w][1] = l1; s_wred[w][2] = l2; s_wred[w][3] = l3;
    }
    __syncthreads();

    // tid 0 writes all 4 partials (so its threadfence orders them), then tickets
    if (tid == 0) {
        #pragma unroll
        for (int g = 0; g < G; g++) {
            float s = 0.f;
            #pragma unroll
            for (int w = 0; w < 8; w++) s += s_wred[w][g];
            g_partials[n * CH + c0 + g] = s;
        }
        __threadfence();
        s_elect = (atomicAdd(&g_done, 1) == NBLK - 1) ? 1 : 0;
    }
    __syncthreads();

    // Last-done block finalizes (fixed-order, deterministic)
    if (s_elect) {
        const int w    = tid >> 5;   // batch index
        const int lane = tid & 31;
        float s = 0.f;
        #pragma unroll
        for (int j = 0; j < 8; j++)
            s += __ldcg(&g_partials[w * CH + j * 32 + lane]);
        #pragma unroll
        for (int off = 16; off > 0; off >>= 1)
            s += __shfl_down_sync(0xFFFFFFFFu, s, off);
        if (lane == 0) {
            s_loss[w] = s / ((float)__ldcg(&g_cnt[w]) + 1e-6f);
            g_cnt[w] = 0;        // reset for next graph replay (A rebuilds it)
        }
        __syncthreads();
        if (tid == 0) {
            float m = 0.f;
            #pragma unroll
            for (int i = 0; i < NB; i++) m += s_loss[i];
            out[0] = -2.0f * (m * (1.0f / (float)NB));
            g_done = 0;          // self-reset for next graph replay
        }
    }
}

extern "C" void kernel_launch(void* const* d_in, const int* in_sizes, int n_in,
                              void* d_out, int out_size)
{
    const float* q  = (const float*)d_in[0];
    const float* k  = (const float*)d_in[1];
    const float* cq = (const float*)d_in[2];
    const float* ck = (const float*)d_in[3];
    float* out = (float*)d_out;

    pixpro_mask<<<NB * PP / 256, 256>>>(cq, ck);
    pixpro_dot<<<NBLK, 256>>>(q, k, out);
}